// round 6
// baseline (speedup 1.0000x reference)
#include <cuda_runtime.h>
#include <math.h>

// ---------------- problem constants ----------------
#define BATCH 128
#define TLEN  300
#define LW    28
#define OUTN  28
#define SPN   7
#define EN    20
#define HN    256
#define WN    273          // T - L + 1
#define WOUT  245          // W - OUT
#define FIN   49           // L + 1 + E
#define BD    10           // distinct batch rows (b % 10)
#define MROWS (WN*BD)      // 2730

// output region boundaries (float32 elements, tuple order)
#define P0 878080          // prediction_values (245,128,28)
#define P1 1756160         // actual_values    (245,128,28)
#define P2 1759744         // holdout_prediction (128,28)
#define P3 2738176         // rnn_out (273,128,28)
#define P4 2741760         // hav (128,28)
#define P5 2745344         // hav_norm (128,28)

// ---------------- device scratch (no cudaMalloc allowed) ----------------
__device__ float g_Sfull[BATCH*307];
__device__ float g_levels[BATCH*TLEN];
__device__ float g_win[MROWS*FIN];
__device__ float g_Z[MROWS*1024];
__device__ float g_hA[MROWS*HN];
__device__ float g_hB[MROWS*HN];
__device__ float g_cring[6*BD*HN];
__device__ float g_rnn[MROWS*OUTN];

// ---------------- ES (Holt-Winters) smoothing: 1 block, 1 thread / series ----
__global__ void es_kernel(const float* __restrict__ x,
                          const float* __restrict__ alpha_raw,
                          const float* __restrict__ gamma_raw,
                          const float* __restrict__ init_seas)
{
    int b = threadIdx.x;
    if (b >= BATCH) return;
    float a = 1.f/(1.f+expf(-alpha_raw[b]));
    float g = 1.f/(1.f+expf(-gamma_raw[b]));
    float s0 = 0.f;
    for (int k = 0; k < SPN; k++) {
        float s = expf(init_seas[b*SPN + k]);
        g_Sfull[b*307 + k] = s;
        if (k == 0) s0 = s;
    }
    g_Sfull[b*307 + 7] = s0;
    float level = x[b*TLEN] / s0;
    g_levels[b*TLEN] = level;
    for (int t = 1; t < TLEN; t++) {
        float xt = x[b*TLEN + t];
        float s  = g_Sfull[b*307 + t];              // seasonal consumed at t
        float lvl  = a*(xt/s) + (1.f - a)*level;
        float snew = g*(xt/lvl) + (1.f - g)*s;
        g_Sfull[b*307 + t + 7] = snew;              // produced seasonal
        level = lvl;
        g_levels[b*TLEN + t] = lvl;
    }
}

// ---------------- build window_input (only 10 distinct batch rows) ----------
__global__ void build_win(const float* __restrict__ x,
                          const float* __restrict__ cats,
                          const float* __restrict__ myp)
{
    int idx = blockIdx.x*blockDim.x + threadIdx.x;
    if (idx >= MROWS*FIN) return;
    int f  = idx % FIN;
    int r  = idx / FIN;
    int bb = r % BD;
    int w  = r / BD;
    float v;
    if (f < LW) {
        int tt = w + f;
        v = x[bb*TLEN + tt] / g_Sfull[bb*307 + tt] / g_levels[bb*TLEN + 27 + w];
    } else if (f < LW + EN) {
        v = cats[bb*EN + (f - LW)];
    } else {
        v = myp[0];
    }
    g_win[idx] = v;
}

// ---------------- generic SGEMM-NT: C[m][n] = act(bias[n] + A[m,:]·B[n,:]) ---
// A: MxK row-major, B: NxK row-major, bias: N. Tiles 64x64, BK=16, 256 thr, 4x4.
template<int ACT>
__global__ void sgemm_nt(const float* __restrict__ A,
                         const float* __restrict__ Bm,
                         const float* __restrict__ bias,
                         float* __restrict__ C,
                         int M, int N, int K)
{
    __shared__ float As[16][64];
    __shared__ float Bs[16][64];
    const int tid = threadIdx.x;
    const int mBase = blockIdx.y * 64;
    const int nBase = blockIdx.x * 64;
    const int lr = tid >> 2;           // 0..63
    const int lk = (tid & 3) << 2;     // 0,4,8,12
    const int tx = tid & 15, ty = tid >> 4;
    float acc[4][4] = {};

    for (int k0 = 0; k0 < K; k0 += 16) {
        {
            const int m = mBase + lr;
            const int n = nBase + lr;
            #pragma unroll
            for (int i = 0; i < 4; i++) {
                int k = k0 + lk + i;
                As[lk+i][lr] = (m < M && k < K) ? A[m*K + k] : 0.f;
                Bs[lk+i][lr] = (n < N && k < K) ? Bm[n*K + k] : 0.f;
            }
        }
        __syncthreads();
        #pragma unroll
        for (int kk = 0; kk < 16; kk++) {
            const float4 a4 = *(const float4*)&As[kk][ty << 2];
            const float4 b4 = *(const float4*)&Bs[kk][tx << 2];
            float av[4] = {a4.x, a4.y, a4.z, a4.w};
            float bv[4] = {b4.x, b4.y, b4.z, b4.w};
            #pragma unroll
            for (int i = 0; i < 4; i++)
                #pragma unroll
                for (int j = 0; j < 4; j++)
                    acc[i][j] += av[i] * bv[j];
        }
        __syncthreads();
    }

    #pragma unroll
    for (int i = 0; i < 4; i++) {
        int m = mBase + (ty << 2) + i;
        if (m >= M) continue;
        #pragma unroll
        for (int j = 0; j < 4; j++) {
            int n = nBase + (tx << 2) + j;
            if (n >= N) continue;
            float v = acc[i][j] + bias[n];
            if (ACT == 1) v = tanhf(v);
            C[m*N + n] = v;
        }
    }
}

// ---------------- fused recurrent LSTM step ---------------------------------
// One launch handles timesteps t0 .. t0+gridDim.z-1 (one dilation group).
// Block: 256 threads = 16 rows (10 live) x 16 u-columns. Each thread owns the
// 4 gate dot-products (i,f,g,o) for its (r,u) cell, then applies the gates.
// grid: (16 u-tiles, 1, nT)
__global__ void lstm_step(const float* __restrict__ Z,
                          const float* __restrict__ Whh,
                          float* __restrict__ h,
                          float* __restrict__ cring,
                          int t0, int d)
{
    const int t  = t0 + blockIdx.z;
    const int u0 = blockIdx.x * 16;
    __shared__ float As[32][16];                       // [k][r]  h_prev
    __shared__ __align__(16) float Bs2[32][16][4];     // [k][u][gate]
    const int tid = threadIdx.x;
    const int r = tid & 15;
    const int u = tid >> 4;
    const bool hasPrev = (t >= d);

    float acc_i = 0.f, acc_f = 0.f, acc_g = 0.f, acc_o = 0.f;

    for (int k0 = 0; k0 < HN; k0 += 32) {
        // load h_prev tile: 32k x 16r, 2 per thread
        {
            int lr = tid >> 4;            // 0..15
            int lk = (tid & 15) * 2;      // 0..30
            float v0 = 0.f, v1 = 0.f;
            if (hasPrev && lr < BD) {
                const float* p = h + ((t - d)*BD + lr)*HN + k0 + lk;
                v0 = p[0]; v1 = p[1];
            }
            As[lk][lr]   = v0;
            As[lk+1][lr] = v1;
        }
        // load Whh tile: 64 rows (16u x 4g) x 32 k, as float4, 2 per thread
        #pragma unroll
        for (int j = 0; j < 2; j++) {
            int q = tid + j*256;          // float4 index 0..511
            int rowsel = q >> 3;          // 0..63
            int gg = rowsel >> 4;         // gate 0..3
            int uu = rowsel & 15;
            int kq = (q & 7) * 4;         // 0..28
            const float4 w4 = *(const float4*)&Whh[(gg*HN + u0 + uu)*HN + k0 + kq];
            Bs2[kq+0][uu][gg] = w4.x;
            Bs2[kq+1][uu][gg] = w4.y;
            Bs2[kq+2][uu][gg] = w4.z;
            Bs2[kq+3][uu][gg] = w4.w;
        }
        __syncthreads();
        #pragma unroll
        for (int k = 0; k < 32; k++) {
            float a = As[k][r];
            const float4 w = *(const float4*)&Bs2[k][u][0];
            acc_i += a * w.x;
            acc_f += a * w.y;
            acc_g += a * w.z;
            acc_o += a * w.w;
        }
        __syncthreads();
    }

    if (r < BD) {
        const int uG = u0 + u;
        const float* zp = Z + (t*BD + r)*1024;
        float zi = acc_i + zp[uG];
        float zf = acc_f + zp[256 + uG];
        float zg = acc_g + zp[512 + uG];
        float zo = acc_o + zp[768 + uG];
        int cidx = ((t % d)*BD + r)*HN + uG;
        float c_old = hasPrev ? cring[cidx] : 0.f;
        float ig = 1.f/(1.f + expf(-zi));
        float fg = 1.f/(1.f + expf(-zf));
        float og = 1.f/(1.f + expf(-zo));
        float c_new = fg*c_old + ig*tanhf(zg);
        cring[cidx] = c_new;
        h[(t*BD + r)*HN + uG] = og*tanhf(c_new);
    }
}

// ---------------- residual add: hA += hB ------------------------------------
__global__ void add_residual(float* __restrict__ a, const float* __restrict__ b)
{
    int i = blockIdx.x*blockDim.x + threadIdx.x;
    if (i < MROWS*HN) a[i] += b[i];
}

// ---------------- assemble all six outputs ----------------------------------
__global__ void outputs_kernel(const float* __restrict__ x,
                               const float* __restrict__ val,
                               float* __restrict__ out, int out_size)
{
    for (int idx = blockIdx.x*blockDim.x + threadIdx.x; idx < out_size;
         idx += gridDim.x*blockDim.x)
    {
        float v = 0.f;
        if (idx < P0) {                              // prediction_values
            int w = idx / 3584; int rem = idx - w*3584;
            int b = rem / 28;   int j = rem - b*28;
            v = g_rnn[(w*BD + (b % BD))*OUTN + j];
        } else if (idx < P1) {                       // actual_values
            int i = idx - P0;
            int wo = i / 3584; int rem = i - wo*3584;
            int b = rem / 28;  int j = rem - b*28;
            int tt = 28 + wo + j;
            v = x[b*TLEN + tt] / g_Sfull[b*307 + tt] / g_levels[b*TLEN + 27 + wo];
        } else if (idx < P2) {                       // holdout_prediction
            int i = idx - P1;
            int b = i / 28; int j = i - b*28;
            int k = 286 + j; if (k >= 307) k -= 7;   // S_ext tail wrap
            float hh = g_rnn[(272*BD + (b % BD))*OUTN + j]
                       * g_Sfull[b*307 + k] * g_levels[b*TLEN + 299];
            v = hh > 0.f ? hh : 0.f;
        } else if (idx < P3) {                       // rnn_out
            int i = idx - P2;
            int w = i / 3584; int rem = i - w*3584;
            int b = rem / 28; int j = rem - b*28;
            v = g_rnn[(w*BD + (b % BD))*OUTN + j];
        } else if (idx < P4) {                       // hav (val passthrough)
            v = val[idx - P3];
        } else if (idx < P5) {                       // hav_norm
            int i = idx - P4;
            int b = i / 28; int j = i - b*28;
            int k = 286 + j; if (k >= 307) k -= 7;
            v = val[b*28 + j] / g_Sfull[b*307 + k] / g_levels[b*TLEN + 299];
        }
        out[idx] = v;
    }
}

// ---------------- host launcher ----------------------------------------------
extern "C" void kernel_launch(void* const* d_in, const int* in_sizes, int n_in,
                              void* d_out, int out_size)
{
    const float* x      = (const float*)d_in[0];
    const float* val    = (const float*)d_in[1];
    const float* alpha  = (const float*)d_in[2];
    const float* gamma  = (const float*)d_in[3];
    const float* iseas  = (const float*)d_in[4];
    const float* cats   = (const float*)d_in[5];
    const float* myp    = (const float*)d_in[6];
    const float* Wih1   = (const float*)d_in[7];
    const float* Whh1   = (const float*)d_in[8];
    const float* b1     = (const float*)d_in[9];
    const float* Wih2   = (const float*)d_in[10];
    const float* Whh2   = (const float*)d_in[11];
    const float* b2     = (const float*)d_in[12];
    const float* Wih3   = (const float*)d_in[13];
    const float* Whh3   = (const float*)d_in[14];
    const float* b3     = (const float*)d_in[15];
    const float* Wih4   = (const float*)d_in[16];
    const float* Whh4   = (const float*)d_in[17];
    const float* b4     = (const float*)d_in[18];
    const float* lW     = (const float*)d_in[19];
    const float* lb     = (const float*)d_in[20];
    const float* sW     = (const float*)d_in[21];
    const float* sb     = (const float*)d_in[22];

    float *pWin, *pZ, *pHA, *pHB, *pC, *pRnn;
    cudaGetSymbolAddress((void**)&pWin, g_win);
    cudaGetSymbolAddress((void**)&pZ,   g_Z);
    cudaGetSymbolAddress((void**)&pHA,  g_hA);
    cudaGetSymbolAddress((void**)&pHB,  g_hB);
    cudaGetSymbolAddress((void**)&pC,   g_cring);
    cudaGetSymbolAddress((void**)&pRnn, g_rnn);

    // 1) exponential smoothing + seasonal states
    es_kernel<<<1, 128>>>(x, alpha, gamma, iseas);

    // 2) normalized window inputs (batch collapsed to 10 distinct rows)
    build_win<<<(MROWS*FIN + 255)/256, 256>>>(x, cats, myp);

    dim3 gBig(16, (MROWS + 63)/64);   // N=1024 GEMMs

    // ---- layer 1 (d=1) ----
    sgemm_nt<0><<<gBig, 256>>>(pWin, Wih1, b1, pZ, MROWS, 1024, FIN);
    for (int t = 0; t < WN; t++)
        lstm_step<<<dim3(16,1,1), 256>>>(pZ, Whh1, pHA, pC, t, 1);

    // ---- layer 2 (d=2) -> h1 kept in hB for residual ----
    sgemm_nt<0><<<gBig, 256>>>(pHA, Wih2, b2, pZ, MROWS, 1024, HN);
    for (int n = 0; n < 137; n++) {
        int t0 = 2*n; int nT = (WN - t0) < 2 ? (WN - t0) : 2;
        lstm_step<<<dim3(16,1,nT), 256>>>(pZ, Whh2, pHB, pC, t0, 2);
    }

    // ---- layer 3 (d=2) ----
    sgemm_nt<0><<<gBig, 256>>>(pHB, Wih3, b3, pZ, MROWS, 1024, HN);
    for (int n = 0; n < 137; n++) {
        int t0 = 2*n; int nT = (WN - t0) < 2 ? (WN - t0) : 2;
        lstm_step<<<dim3(16,1,nT), 256>>>(pZ, Whh3, pHA, pC, t0, 2);
    }

    // ---- layer 4 (d=6) ---- (input GEMM consumes hA, recurrence rewrites hA)
    sgemm_nt<0><<<gBig, 256>>>(pHA, Wih4, b4, pZ, MROWS, 1024, HN);
    for (int n = 0; n < 46; n++) {
        int t0 = 6*n; int nT = (WN - t0) < 6 ? (WN - t0) : 6;
        lstm_step<<<dim3(16,1,nT), 256>>>(pZ, Whh4, pHA, pC, t0, 6);
    }

    // ---- residual: h2 = lstm4(...) + h1 ----
    add_residual<<<(MROWS*HN + 255)/256, 256>>>(pHA, pHB);

    // ---- linear + tanh, then score ----
    sgemm_nt<1><<<dim3(4, (MROWS+63)/64), 256>>>(pHA, lW, lb, pHB, MROWS, HN, HN);
    sgemm_nt<0><<<dim3(1, (MROWS+63)/64), 256>>>(pHB, sW, sb, pRnn, MROWS, OUTN, HN);

    // ---- assemble outputs ----
    outputs_kernel<<<1024, 256>>>(x, val, (float*)d_out, out_size);
}

// round 7
// speedup vs baseline: 1.2485x; 1.2485x over previous
#include <cuda_runtime.h>
#include <math.h>

// ---------------- problem constants ----------------
#define BATCH 128
#define TLEN  300
#define LW    28
#define OUTN  28
#define SPN   7
#define EN    20
#define HN    256
#define WN    273          // T - L + 1
#define WOUT  245          // W - OUT
#define FIN   49           // L + 1 + E
#define BD    10           // distinct batch rows (b % 10)
#define MROWS (WN*BD)      // 2730
#define NBLK  64           // persistent recurrence blocks

// output region boundaries (float32 elements, tuple order)
#define P0 878080          // prediction_values (245,128,28)
#define P1 1756160         // actual_values    (245,128,28)
#define P2 1759744         // holdout_prediction (128,28)
#define P3 2738176         // rnn_out (273,128,28)
#define P4 2741760         // hav (128,28)
#define P5 2745344         // hav_norm (128,28)

// ---------------- device scratch (no cudaMalloc allowed) ----------------
__device__ float g_Sfull[BATCH*307];
__device__ float g_levels[BATCH*TLEN];
__device__ float g_win[MROWS*FIN];
__device__ float g_Z[MROWS*1024];
__device__ float g_hA[MROWS*HN];
__device__ float g_hB[MROWS*HN];
__device__ float g_cring[6*BD*HN];
__device__ float g_rnn[MROWS*OUTN];

// grid-barrier state (monotonic; never reset -> safe across graph replays)
__device__ unsigned long long g_arrive = 0ull;
__device__ volatile unsigned long long g_release = 0ull;

// ---------------- ES (Holt-Winters) smoothing ----------------
__global__ void es_kernel(const float* __restrict__ x,
                          const float* __restrict__ alpha_raw,
                          const float* __restrict__ gamma_raw,
                          const float* __restrict__ init_seas)
{
    int b = threadIdx.x;
    if (b >= BATCH) return;
    float a = 1.f/(1.f+expf(-alpha_raw[b]));
    float g = 1.f/(1.f+expf(-gamma_raw[b]));
    float s0 = 0.f;
    for (int k = 0; k < SPN; k++) {
        float s = expf(init_seas[b*SPN + k]);
        g_Sfull[b*307 + k] = s;
        if (k == 0) s0 = s;
    }
    g_Sfull[b*307 + 7] = s0;
    float level = x[b*TLEN] / s0;
    g_levels[b*TLEN] = level;
    for (int t = 1; t < TLEN; t++) {
        float xt = x[b*TLEN + t];
        float s  = g_Sfull[b*307 + t];
        float lvl  = a*(xt/s) + (1.f - a)*level;
        float snew = g*(xt/lvl) + (1.f - g)*s;
        g_Sfull[b*307 + t + 7] = snew;
        level = lvl;
        g_levels[b*TLEN + t] = lvl;
    }
}

// ---------------- build window_input (10 distinct batch rows) ----------
__global__ void build_win(const float* __restrict__ x,
                          const float* __restrict__ cats,
                          const float* __restrict__ myp)
{
    int idx = blockIdx.x*blockDim.x + threadIdx.x;
    if (idx >= MROWS*FIN) return;
    int f  = idx % FIN;
    int r  = idx / FIN;
    int bb = r % BD;
    int w  = r / BD;
    float v;
    if (f < LW) {
        int tt = w + f;
        v = x[bb*TLEN + tt] / g_Sfull[bb*307 + tt] / g_levels[bb*TLEN + 27 + w];
    } else if (f < LW + EN) {
        v = cats[bb*EN + (f - LW)];
    } else {
        v = myp[0];
    }
    g_win[idx] = v;
}

// ---------------- generic SGEMM-NT (64x64, used for K=49 and N=28) ---------
template<int ACT>
__global__ void sgemm_nt(const float* __restrict__ A,
                         const float* __restrict__ Bm,
                         const float* __restrict__ bias,
                         float* __restrict__ C,
                         int M, int N, int K)
{
    __shared__ float As[16][64];
    __shared__ float Bs[16][64];
    const int tid = threadIdx.x;
    const int mBase = blockIdx.y * 64;
    const int nBase = blockIdx.x * 64;
    const int lr = tid >> 2;
    const int lk = (tid & 3) << 2;
    const int tx = tid & 15, ty = tid >> 4;
    float acc[4][4] = {};

    for (int k0 = 0; k0 < K; k0 += 16) {
        {
            const int m = mBase + lr;
            const int n = nBase + lr;
            #pragma unroll
            for (int i = 0; i < 4; i++) {
                int k = k0 + lk + i;
                As[lk+i][lr] = (m < M && k < K) ? A[m*K + k] : 0.f;
                Bs[lk+i][lr] = (n < N && k < K) ? Bm[n*K + k] : 0.f;
            }
        }
        __syncthreads();
        #pragma unroll
        for (int kk = 0; kk < 16; kk++) {
            const float4 a4 = *(const float4*)&As[kk][ty << 2];
            const float4 b4 = *(const float4*)&Bs[kk][tx << 2];
            float av[4] = {a4.x, a4.y, a4.z, a4.w};
            float bv[4] = {b4.x, b4.y, b4.z, b4.w};
            #pragma unroll
            for (int i = 0; i < 4; i++)
                #pragma unroll
                for (int j = 0; j < 4; j++)
                    acc[i][j] += av[i] * bv[j];
        }
        __syncthreads();
    }

    #pragma unroll
    for (int i = 0; i < 4; i++) {
        int m = mBase + (ty << 2) + i;
        if (m >= M) continue;
        #pragma unroll
        for (int j = 0; j < 4; j++) {
            int n = nBase + (tx << 2) + j;
            if (n >= N) continue;
            float v = acc[i][j] + bias[n];
            if (ACT == 1) v = tanhf(v);
            C[m*N + n] = v;
        }
    }
}

// ---------------- fast SGEMM-NT 128x128, BK=8, 8x8/thread (K%8==0, K-aligned) --
template<int ACT>
__global__ void sgemm128(const float* __restrict__ A,
                         const float* __restrict__ Bm,
                         const float* __restrict__ bias,
                         float* __restrict__ C,
                         int M, int N, int K)
{
    __shared__ float As[8][132];
    __shared__ float Bs[8][132];
    const int tid = threadIdx.x;
    const int mBase = blockIdx.y * 128;
    const int nBase = blockIdx.x * 128;
    const int tx = tid & 15, ty = tid >> 4;
    const int lrow = tid >> 1;
    const int lhalf = (tid & 1) * 4;
    float acc[8][8] = {};

    for (int k0 = 0; k0 < K; k0 += 8) {
        {
            int m = mBase + lrow;
            float4 v = (m < M) ? *(const float4*)&A[m*K + k0 + lhalf]
                               : make_float4(0.f,0.f,0.f,0.f);
            As[lhalf+0][lrow] = v.x; As[lhalf+1][lrow] = v.y;
            As[lhalf+2][lrow] = v.z; As[lhalf+3][lrow] = v.w;
            int n = nBase + lrow;
            float4 w = (n < N) ? *(const float4*)&Bm[n*K + k0 + lhalf]
                               : make_float4(0.f,0.f,0.f,0.f);
            Bs[lhalf+0][lrow] = w.x; Bs[lhalf+1][lrow] = w.y;
            Bs[lhalf+2][lrow] = w.z; Bs[lhalf+3][lrow] = w.w;
        }
        __syncthreads();
        #pragma unroll
        for (int kk = 0; kk < 8; kk++) {
            float a[8], b[8];
            *(float4*)&a[0] = *(const float4*)&As[kk][ty*8];
            *(float4*)&a[4] = *(const float4*)&As[kk][ty*8+4];
            *(float4*)&b[0] = *(const float4*)&Bs[kk][tx*8];
            *(float4*)&b[4] = *(const float4*)&Bs[kk][tx*8+4];
            #pragma unroll
            for (int i = 0; i < 8; i++)
                #pragma unroll
                for (int j = 0; j < 8; j++)
                    acc[i][j] = fmaf(a[i], b[j], acc[i][j]);
        }
        __syncthreads();
    }
    #pragma unroll
    for (int i = 0; i < 8; i++) {
        int m = mBase + ty*8 + i;
        if (m >= M) continue;
        #pragma unroll
        for (int j = 0; j < 8; j++) {
            int n = nBase + tx*8 + j;
            if (n >= N) continue;
            float v = acc[i][j] + bias[n];
            if (ACT == 1) v = tanhf(v);
            C[m*N + n] = v;
        }
    }
}

// ---------------- persistent per-layer LSTM recurrence ----------------------
// 64 blocks x 256 threads, all co-resident. Block owns 4 hidden units (all 4
// gates = 16 Whh rows) cached in SMEM for the whole layer. Timesteps iterate
// in-kernel, separated by a software grid barrier. Dilated layers run their d
// independent chains inside one barrier interval.
// Thread map: tid = kpart(4) + 4*r(16) + 64*ulocal(4). Live work: r<10.
__device__ __forceinline__ void grid_sync_dev(unsigned long long base,
                                              unsigned long long it)
{
    __syncthreads();
    if (threadIdx.x == 0) {
        __threadfence();
        unsigned long long need = (base + it + 1) * (unsigned long long)NBLK;
        unsigned long long old = atomicAdd(&g_arrive, 1ull);
        if (old + 1ull == need) {
            g_release = base + it + 1ull;
        } else {
            while (g_release < base + it + 1ull) { }
        }
        __threadfence();
    }
    __syncthreads();
}

__global__ void __launch_bounds__(256, 1)
lstm_layer(const float* __restrict__ Z,
           const float* __restrict__ Whh,
           float* __restrict__ h,
           float* __restrict__ cring,
           int d)
{
    __shared__ __align__(16) float Ws[4*256*4];   // [(ul*256+k)*4 + gate], 16KB
    __shared__ float hs[16*260];                  // padded h_prev rows, 16.6KB
    __shared__ unsigned long long s_base;

    const int tid = threadIdx.x;
    const int u0  = blockIdx.x * 4;
    if (tid == 0) s_base = g_release;             // stable at launch entry

    // one-time Whh slice load: rows g*HN + (u0+ul), interleaved by gate
    {
        int rowi = tid >> 4;          // 0..15
        int g  = rowi >> 2;
        int ul = rowi & 3;
        const float* src = Whh + (g*HN + u0 + ul)*HN;
        int kb = (tid & 15) * 16;
        #pragma unroll
        for (int k = kb; k < kb + 16; k++)
            Ws[(ul*256 + k)*4 + g] = src[k];
    }
    __syncthreads();

    const int kp = tid & 3;
    const int r  = (tid >> 2) & 15;
    const int ul = tid >> 6;
    const int uG = u0 + ul;
    const bool cell = (kp == 0) && (r < BD);
    const float*  hp = &hs[r*260 + kp];
    const float4* wp = ((const float4*)Ws) + ul*256 + kp;

    const int nIter = (WN + d - 1) / d;
    const unsigned long long base = s_base;

    for (int it = 0; it < nIter; it++) {
        for (int c = 0; c < d; c++) {
            const int t = it*d + c;
            if (t < WN) {
                const bool hasPrev = (t >= d);
                // cooperative load h_prev -> SMEM (coalesced)
                for (int j = tid; j < BD*HN; j += 256) {
                    int rr = j >> 8, kk = j & 255;
                    hs[rr*260 + kk] = hasPrev ? h[((t-d)*BD + rr)*HN + kk] : 0.f;
                }
                __syncthreads();

                float ai = 0.f, af = 0.f, ag = 0.f, ao = 0.f;
                #pragma unroll 16
                for (int i = 0; i < 64; i++) {
                    float  a = hp[4*i];
                    float4 w = wp[4*i];
                    ai = fmaf(a, w.x, ai);
                    af = fmaf(a, w.y, af);
                    ag = fmaf(a, w.z, ag);
                    ao = fmaf(a, w.w, ao);
                }
                // reduce over kpart (lanes xor 1, xor 2)
                ai += __shfl_xor_sync(0xffffffffu, ai, 1);
                af += __shfl_xor_sync(0xffffffffu, af, 1);
                ag += __shfl_xor_sync(0xffffffffu, ag, 1);
                ao += __shfl_xor_sync(0xffffffffu, ao, 1);
                ai += __shfl_xor_sync(0xffffffffu, ai, 2);
                af += __shfl_xor_sync(0xffffffffu, af, 2);
                ag += __shfl_xor_sync(0xffffffffu, ag, 2);
                ao += __shfl_xor_sync(0xffffffffu, ao, 2);

                if (cell) {
                    const float* zp = Z + (t*BD + r)*1024;
                    float zi = ai + zp[uG];
                    float zf = af + zp[256 + uG];
                    float zg = ag + zp[512 + uG];
                    float zo = ao + zp[768 + uG];
                    int cidx = ((t % d)*BD + r)*HN + uG;
                    float c_old = hasPrev ? cring[cidx] : 0.f;
                    float ig = 1.f/(1.f + expf(-zi));
                    float fg = 1.f/(1.f + expf(-zf));
                    float og = 1.f/(1.f + expf(-zo));
                    float c_new = fg*c_old + ig*tanhf(zg);
                    cring[cidx] = c_new;
                    h[(t*BD + r)*HN + uG] = og*tanhf(c_new);
                }
                __syncthreads();   // hs reuse safety for next chain
            }
        }
        grid_sync_dev(base, (unsigned long long)it);
    }
}

// ---------------- residual add: hA += hB ------------------------------------
__global__ void add_residual(float* __restrict__ a, const float* __restrict__ b)
{
    int i = blockIdx.x*blockDim.x + threadIdx.x;
    if (i < MROWS*HN) a[i] += b[i];
}

// ---------------- assemble all six outputs ----------------------------------
__global__ void outputs_kernel(const float* __restrict__ x,
                               const float* __restrict__ val,
                               float* __restrict__ out, int out_size)
{
    for (int idx = blockIdx.x*blockDim.x + threadIdx.x; idx < out_size;
         idx += gridDim.x*blockDim.x)
    {
        float v = 0.f;
        if (idx < P0) {                              // prediction_values
            int w = idx / 3584; int rem = idx - w*3584;
            int b = rem / 28;   int j = rem - b*28;
            v = g_rnn[(w*BD + (b % BD))*OUTN + j];
        } else if (idx < P1) {                       // actual_values
            int i = idx - P0;
            int wo = i / 3584; int rem = i - wo*3584;
            int b = rem / 28;  int j = rem - b*28;
            int tt = 28 + wo + j;
            v = x[b*TLEN + tt] / g_Sfull[b*307 + tt] / g_levels[b*TLEN + 27 + wo];
        } else if (idx < P2) {                       // holdout_prediction
            int i = idx - P1;
            int b = i / 28; int j = i - b*28;
            int k = 286 + j; if (k >= 307) k -= 7;
            float hh = g_rnn[(272*BD + (b % BD))*OUTN + j]
                       * g_Sfull[b*307 + k] * g_levels[b*TLEN + 299];
            v = hh > 0.f ? hh : 0.f;
        } else if (idx < P3) {                       // rnn_out
            int i = idx - P2;
            int w = i / 3584; int rem = i - w*3584;
            int b = rem / 28; int j = rem - b*28;
            v = g_rnn[(w*BD + (b % BD))*OUTN + j];
        } else if (idx < P4) {                       // hav
            v = val[idx - P3];
        } else if (idx < P5) {                       // hav_norm
            int i = idx - P4;
            int b = i / 28; int j = i - b*28;
            int k = 286 + j; if (k >= 307) k -= 7;
            v = val[b*28 + j] / g_Sfull[b*307 + k] / g_levels[b*TLEN + 299];
        }
        out[idx] = v;
    }
}

// ---------------- host launcher ----------------------------------------------
extern "C" void kernel_launch(void* const* d_in, const int* in_sizes, int n_in,
                              void* d_out, int out_size)
{
    const float* x      = (const float*)d_in[0];
    const float* val    = (const float*)d_in[1];
    const float* alpha  = (const float*)d_in[2];
    const float* gamma  = (const float*)d_in[3];
    const float* iseas  = (const float*)d_in[4];
    const float* cats   = (const float*)d_in[5];
    const float* myp    = (const float*)d_in[6];
    const float* Wih1   = (const float*)d_in[7];
    const float* Whh1   = (const float*)d_in[8];
    const float* b1     = (const float*)d_in[9];
    const float* Wih2   = (const float*)d_in[10];
    const float* Whh2   = (const float*)d_in[11];
    const float* b2     = (const float*)d_in[12];
    const float* Wih3   = (const float*)d_in[13];
    const float* Whh3   = (const float*)d_in[14];
    const float* b3     = (const float*)d_in[15];
    const float* Wih4   = (const float*)d_in[16];
    const float* Whh4   = (const float*)d_in[17];
    const float* b4     = (const float*)d_in[18];
    const float* lW     = (const float*)d_in[19];
    const float* lb     = (const float*)d_in[20];
    const float* sW     = (const float*)d_in[21];
    const float* sb     = (const float*)d_in[22];

    float *pWin, *pZ, *pHA, *pHB, *pC, *pRnn;
    cudaGetSymbolAddress((void**)&pWin, g_win);
    cudaGetSymbolAddress((void**)&pZ,   g_Z);
    cudaGetSymbolAddress((void**)&pHA,  g_hA);
    cudaGetSymbolAddress((void**)&pHB,  g_hB);
    cudaGetSymbolAddress((void**)&pC,   g_cring);
    cudaGetSymbolAddress((void**)&pRnn, g_rnn);

    // 1) exponential smoothing + seasonals
    es_kernel<<<1, 128>>>(x, alpha, gamma, iseas);

    // 2) normalized window inputs (batch collapsed to 10 distinct rows)
    build_win<<<(MROWS*FIN + 255)/256, 256>>>(x, cats, myp);

    dim3 gBig128(8, (MROWS + 127)/128);   // N=1024, K=256 GEMMs

    // ---- layer 1 (d=1): K=49 input GEMM (unaligned K -> 64x64 kernel) ----
    sgemm_nt<0><<<dim3(16, (MROWS+63)/64), 256>>>(pWin, Wih1, b1, pZ, MROWS, 1024, FIN);
    lstm_layer<<<NBLK, 256>>>(pZ, Whh1, pHA, pC, 1);

    // ---- layer 2 (d=2) -> h1 kept in hB for residual ----
    sgemm128<0><<<gBig128, 256>>>(pHA, Wih2, b2, pZ, MROWS, 1024, HN);
    lstm_layer<<<NBLK, 256>>>(pZ, Whh2, pHB, pC, 2);

    // ---- layer 3 (d=2) ----
    sgemm128<0><<<gBig128, 256>>>(pHB, Wih3, b3, pZ, MROWS, 1024, HN);
    lstm_layer<<<NBLK, 256>>>(pZ, Whh3, pHA, pC, 2);

    // ---- layer 4 (d=6) ----
    sgemm128<0><<<gBig128, 256>>>(pHA, Wih4, b4, pZ, MROWS, 1024, HN);
    lstm_layer<<<NBLK, 256>>>(pZ, Whh4, pHA, pC, 6);

    // ---- residual: h2 = lstm4(...) + h1 ----
    add_residual<<<(MROWS*HN + 255)/256, 256>>>(pHA, pHB);

    // ---- linear + tanh, then score ----
    sgemm128<1><<<dim3(2, (MROWS+127)/128), 256>>>(pHA, lW, lb, pHB, MROWS, HN, HN);
    sgemm_nt<0><<<dim3(1, (MROWS+63)/64), 256>>>(pHB, sW, sb, pRnn, MROWS, OUTN, HN);

    // ---- assemble outputs ----
    outputs_kernel<<<1024, 256>>>(x, val, (float*)d_out, out_size);
}

// round 8
// speedup vs baseline: 4.0824x; 3.2700x over previous
#include <cuda_runtime.h>
#include <math.h>
#include <stdint.h>

// ---------------- problem constants ----------------
#define BATCH 128
#define TLEN  300
#define LW    28
#define OUTN  28
#define SPN   7
#define EN    20
#define HN    256
#define WN    273          // T - L + 1
#define WOUT  245          // W - OUT
#define FIN   49           // L + 1 + E
#define BD    10           // distinct batch rows (b % 10)
#define MROWS (WN*BD)      // 2730

// output region boundaries (float32 elements, tuple order)
#define P0 878080          // prediction_values (245,128,28)
#define P1 1756160         // actual_values    (245,128,28)
#define P2 1759744         // holdout_prediction (128,28)
#define P3 2738176         // rnn_out (273,128,28)
#define P4 2741760         // hav (128,28)
#define P5 2745344         // hav_norm (128,28)

// ---------------- device scratch (no cudaMalloc allowed) ----------------
__device__ float g_Sfull[BATCH*307];
__device__ float g_levels[BATCH*TLEN];
__device__ float g_win[MROWS*FIN];
__device__ float g_Z[MROWS*1024];
__device__ float g_hA[MROWS*HN];
__device__ float g_hB[MROWS*HN];
__device__ float g_rnn[MROWS*OUTN];

// ---------------- helpers ----------------
__device__ __forceinline__ uint32_t s2u(const void* p){
    uint32_t a;
    asm("{ .reg .u64 t; cvta.to.shared.u64 t, %1; cvt.u32.u64 %0, t; }"
        : "=r"(a) : "l"(p));
    return a;
}

// ---------------- ES (Holt-Winters) smoothing ----------------
__global__ void es_kernel(const float* __restrict__ x,
                          const float* __restrict__ alpha_raw,
                          const float* __restrict__ gamma_raw,
                          const float* __restrict__ init_seas)
{
    __shared__ float ring[BATCH*SPN];
    int b = threadIdx.x;
    if (b >= BATCH) return;
    float a = 1.f/(1.f+expf(-alpha_raw[b]));
    float g = 1.f/(1.f+expf(-gamma_raw[b]));
    float s0 = 0.f;
    for (int k = 0; k < SPN; k++) {
        float s = expf(init_seas[b*SPN + k]);
        g_Sfull[b*307 + k] = s;
        ring[b*SPN + k] = s;
        if (k == 0) s0 = s;
    }
    g_Sfull[b*307 + 7] = s0;
    float level = x[b*TLEN] / s0;
    g_levels[b*TLEN] = level;
    for (int t = 1; t < TLEN; t++) {
        float xt = x[b*TLEN + t];
        int slot = t % SPN;
        float s = ring[b*SPN + slot];               // seasonal consumed at t
        float lvl  = a*(xt/s) + (1.f - a)*level;
        float snew = g*(xt/lvl) + (1.f - g)*s;
        ring[b*SPN + slot] = snew;                  // slot t%7 == (t+7)%7
        g_Sfull[b*307 + t + 7] = snew;
        level = lvl;
        g_levels[b*TLEN + t] = lvl;
    }
}

// ---------------- build window_input (10 distinct batch rows) ----------
__global__ void build_win(const float* __restrict__ x,
                          const float* __restrict__ cats,
                          const float* __restrict__ myp)
{
    int idx = blockIdx.x*blockDim.x + threadIdx.x;
    if (idx >= MROWS*FIN) return;
    int f  = idx % FIN;
    int r  = idx / FIN;
    int bb = r % BD;
    int w  = r / BD;
    float v;
    if (f < LW) {
        int tt = w + f;
        v = x[bb*TLEN + tt] / g_Sfull[bb*307 + tt] / g_levels[bb*TLEN + 27 + w];
    } else if (f < LW + EN) {
        v = cats[bb*EN + (f - LW)];
    } else {
        v = myp[0];
    }
    g_win[idx] = v;
}

// ---------------- generic SGEMM-NT (64x64, used for K=49 and N=28) ---------
template<int ACT>
__global__ void sgemm_nt(const float* __restrict__ A,
                         const float* __restrict__ Bm,
                         const float* __restrict__ bias,
                         float* __restrict__ C,
                         int M, int N, int K)
{
    __shared__ float As[16][64];
    __shared__ float Bs[16][64];
    const int tid = threadIdx.x;
    const int mBase = blockIdx.y * 64;
    const int nBase = blockIdx.x * 64;
    const int lr = tid >> 2;
    const int lk = (tid & 3) << 2;
    const int tx = tid & 15, ty = tid >> 4;
    float acc[4][4] = {};

    for (int k0 = 0; k0 < K; k0 += 16) {
        {
            const int m = mBase + lr;
            const int n = nBase + lr;
            #pragma unroll
            for (int i = 0; i < 4; i++) {
                int k = k0 + lk + i;
                As[lk+i][lr] = (m < M && k < K) ? A[m*K + k] : 0.f;
                Bs[lk+i][lr] = (n < N && k < K) ? Bm[n*K + k] : 0.f;
            }
        }
        __syncthreads();
        #pragma unroll
        for (int kk = 0; kk < 16; kk++) {
            const float4 a4 = *(const float4*)&As[kk][ty << 2];
            const float4 b4 = *(const float4*)&Bs[kk][tx << 2];
            float av[4] = {a4.x, a4.y, a4.z, a4.w};
            float bv[4] = {b4.x, b4.y, b4.z, b4.w};
            #pragma unroll
            for (int i = 0; i < 4; i++)
                #pragma unroll
                for (int j = 0; j < 4; j++)
                    acc[i][j] += av[i] * bv[j];
        }
        __syncthreads();
    }

    #pragma unroll
    for (int i = 0; i < 4; i++) {
        int m = mBase + (ty << 2) + i;
        if (m >= M) continue;
        #pragma unroll
        for (int j = 0; j < 4; j++) {
            int n = nBase + (tx << 2) + j;
            if (n >= N) continue;
            float v = acc[i][j] + bias[n];
            if (ACT == 1) v = tanhf(v);
            C[m*N + n] = v;
        }
    }
}

// ---------------- fast SGEMM-NT 128x128, BK=8, 8x8/thread (K%8==0) ---------
template<int ACT>
__global__ void sgemm128(const float* __restrict__ A,
                         const float* __restrict__ Bm,
                         const float* __restrict__ bias,
                         float* __restrict__ C,
                         int M, int N, int K)
{
    __shared__ float As[8][132];
    __shared__ float Bs[8][132];
    const int tid = threadIdx.x;
    const int mBase = blockIdx.y * 128;
    const int nBase = blockIdx.x * 128;
    const int tx = tid & 15, ty = tid >> 4;
    const int lrow = tid >> 1;
    const int lhalf = (tid & 1) * 4;
    float acc[8][8] = {};

    for (int k0 = 0; k0 < K; k0 += 8) {
        {
            int m = mBase + lrow;
            float4 v = (m < M) ? *(const float4*)&A[m*K + k0 + lhalf]
                               : make_float4(0.f,0.f,0.f,0.f);
            As[lhalf+0][lrow] = v.x; As[lhalf+1][lrow] = v.y;
            As[lhalf+2][lrow] = v.z; As[lhalf+3][lrow] = v.w;
            int n = nBase + lrow;
            float4 w = (n < N) ? *(const float4*)&Bm[n*K + k0 + lhalf]
                               : make_float4(0.f,0.f,0.f,0.f);
            Bs[lhalf+0][lrow] = w.x; Bs[lhalf+1][lrow] = w.y;
            Bs[lhalf+2][lrow] = w.z; Bs[lhalf+3][lrow] = w.w;
        }
        __syncthreads();
        #pragma unroll
        for (int kk = 0; kk < 8; kk++) {
            float a[8], b[8];
            *(float4*)&a[0] = *(const float4*)&As[kk][ty*8];
            *(float4*)&a[4] = *(const float4*)&As[kk][ty*8+4];
            *(float4*)&b[0] = *(const float4*)&Bs[kk][tx*8];
            *(float4*)&b[4] = *(const float4*)&Bs[kk][tx*8+4];
            #pragma unroll
            for (int i = 0; i < 8; i++)
                #pragma unroll
                for (int j = 0; j < 8; j++)
                    acc[i][j] = fmaf(a[i], b[j], acc[i][j]);
        }
        __syncthreads();
    }
    #pragma unroll
    for (int i = 0; i < 8; i++) {
        int m = mBase + ty*8 + i;
        if (m >= M) continue;
        #pragma unroll
        for (int j = 0; j < 8; j++) {
            int n = nBase + tx*8 + j;
            if (n >= N) continue;
            float v = acc[i][j] + bias[n];
            if (ACT == 1) v = tanhf(v);
            C[m*N + n] = v;
        }
    }
}

// ---------------- cluster-per-chain persistent LSTM recurrence --------------
// One 8-CTA cluster per group of CPC chains (chain = (row, dilation phase),
// enumerated ch = row*D + phase). Each CTA owns 32 hidden units: all 4 gate
// rows of Whh for those units live in REGISTERS (128 regs/thread). Per step:
// packed-f32x2 dot products, shfl reduce, fused gates; the 32-float h slice is
// broadcast to all 8 peer CTAs via st.shared::cluster; hardware cluster
// barrier separates steps. Thread map: tid = kp(2) + 2*g(4) + 8*ul(32).
template<int CPC, int D>
__global__ void __launch_bounds__(256,1) __cluster_dims__(8,1,1)
lstm_chain(const float* __restrict__ Z,
           const float* __restrict__ Whh,
           float* __restrict__ h)
{
    __shared__ float hrep[CPC*2*132];            // per-(chain,kp) padded h half
    __shared__ float stage[2][CPC][256];         // double-buffered full h

    const int tid = threadIdx.x;
    uint32_t rank;
    asm("mov.u32 %0, %%cluster_ctarank;" : "=r"(rank));
    const int U0 = (int)rank * 32;
    const int kp = tid & 1;
    const int g  = (tid >> 1) & 3;
    const int ul = tid >> 3;
    const int chBase = (blockIdx.x >> 3) * CPC;

    // Whh slice -> registers (row = g*HN + U0+ul, k half = kp*128..+128)
    ulonglong2 w[32];
    {
        const ulonglong2* w16 =
            (const ulonglong2*)(Whh + (g*HN + U0 + ul)*HN + kp*128);
        #pragma unroll
        for (int i = 0; i < 32; i++) w[i] = w16[i];
    }
    for (int i = tid; i < CPC*2*132; i += 256) hrep[i] = 0.f;
    float cst[CPC];
    #pragma unroll
    for (int j = 0; j < CPC; j++) cst[j] = 0.f;
    __syncthreads();

    const int lane = tid & 31;
    const int gbase = lane & ~7;
    const bool leader = ((lane & 7) == 0);
    const uint32_t stageAddr = s2u(&stage[0][0][0]);
    const int nIter = (WN + D - 1) / D;

    for (int it = 0; it < nIter; it++) {
        const int p = it & 1;

        // prefetch Z gate values (kp==0 threads carry them past the reduce)
        float zv[CPC];
        #pragma unroll
        for (int j = 0; j < CPC; j++) {
            const int ch = chBase + j;
            const int t = it*D + (ch % D);
            zv[j] = 0.f;
            if (kp == 0 && t < WN)
                zv[j] = Z[(t*BD + ch/D)*1024 + g*HN + U0 + ul];
        }

        #pragma unroll
        for (int j = 0; j < CPC; j++) {
            const int ch  = chBase + j;
            const int row = ch / D;
            const int t   = it*D + (ch % D);
            const ulonglong2* hp = (const ulonglong2*)&hrep[(j*2 + kp)*132];
            unsigned long long p0 = 0ull, p1 = 0ull;   // packed f32 pairs
            #pragma unroll
            for (int i = 0; i < 32; i++) {
                ulonglong2 hv = hp[i];
                asm("fma.rn.f32x2 %0, %1, %2, %0;"
                    : "+l"(p0) : "l"(w[i].x), "l"(hv.x));
                asm("fma.rn.f32x2 %0, %1, %2, %0;"
                    : "+l"(p1) : "l"(w[i].y), "l"(hv.y));
            }
            float v = __uint_as_float((unsigned)p0)
                    + __uint_as_float((unsigned)(p0 >> 32))
                    + __uint_as_float((unsigned)p1)
                    + __uint_as_float((unsigned)(p1 >> 32));
            v += __shfl_xor_sync(0xffffffffu, v, 1);     // kp reduce
            if (kp == 0) v += zv[j];
            float zi = __shfl_sync(0xffffffffu, v, gbase + 0);
            float zf = __shfl_sync(0xffffffffu, v, gbase + 2);
            float zg = __shfl_sync(0xffffffffu, v, gbase + 4);
            float zo = __shfl_sync(0xffffffffu, v, gbase + 6);
            if (leader && t < WN) {
                float ig = 1.f/(1.f + expf(-zi));
                float fg = 1.f/(1.f + expf(-zf));
                float og = 1.f/(1.f + expf(-zo));
                float cn = fg*cst[j] + ig*tanhf(zg);
                cst[j] = cn;
                float hn = og*tanhf(cn);
                h[(t*BD + row)*HN + U0 + ul] = hn;
                // broadcast slice element to all 8 CTAs' stage buffers
                uint32_t off = stageAddr + ((p*CPC + j)*256 + U0 + ul)*4;
                unsigned hu = __float_as_uint(hn);
                #pragma unroll
                for (int rk = 0; rk < 8; rk++) {
                    uint32_t ra;
                    asm volatile("mapa.shared::cluster.u32 %0, %1, %2;"
                                 : "=r"(ra) : "r"(off), "r"(rk));
                    asm volatile("st.shared::cluster.b32 [%0], %1;"
                                 :: "r"(ra), "r"(hu) : "memory");
                }
            }
        }

        asm volatile("barrier.cluster.arrive.aligned;" ::: "memory");
        asm volatile("barrier.cluster.wait.aligned;"   ::: "memory");

        // rebuild padded hrep halves from the freshly staged full h
        {
            const int kpd = tid >> 7;
            const int kl  = tid & 127;
            #pragma unroll
            for (int j = 0; j < CPC; j++)
                hrep[(j*2 + kpd)*132 + kl] = stage[p][j][tid];
        }
        __syncthreads();
    }
}

// ---------------- residual add: hA += hB ------------------------------------
__global__ void add_residual(float* __restrict__ a, const float* __restrict__ b)
{
    int i = blockIdx.x*blockDim.x + threadIdx.x;
    if (i < MROWS*HN) a[i] += b[i];
}

// ---------------- assemble all six outputs ----------------------------------
__global__ void outputs_kernel(const float* __restrict__ x,
                               const float* __restrict__ val,
                               float* __restrict__ out, int out_size)
{
    for (int idx = blockIdx.x*blockDim.x + threadIdx.x; idx < out_size;
         idx += gridDim.x*blockDim.x)
    {
        float v = 0.f;
        if (idx < P0) {                              // prediction_values
            int w = idx / 3584; int rem = idx - w*3584;
            int b = rem / 28;   int j = rem - b*28;
            v = g_rnn[(w*BD + (b % BD))*OUTN + j];
        } else if (idx < P1) {                       // actual_values
            int i = idx - P0;
            int wo = i / 3584; int rem = i - wo*3584;
            int b = rem / 28;  int j = rem - b*28;
            int tt = 28 + wo + j;
            v = x[b*TLEN + tt] / g_Sfull[b*307 + tt] / g_levels[b*TLEN + 27 + wo];
        } else if (idx < P2) {                       // holdout_prediction
            int i = idx - P1;
            int b = i / 28; int j = i - b*28;
            int k = 286 + j; if (k >= 307) k -= 7;
            float hh = g_rnn[(272*BD + (b % BD))*OUTN + j]
                       * g_Sfull[b*307 + k] * g_levels[b*TLEN + 299];
            v = hh > 0.f ? hh : 0.f;
        } else if (idx < P3) {                       // rnn_out
            int i = idx - P2;
            int w = i / 3584; int rem = i - w*3584;
            int b = rem / 28; int j = rem - b*28;
            v = g_rnn[(w*BD + (b % BD))*OUTN + j];
        } else if (idx < P4) {                       // hav
            v = val[idx - P3];
        } else if (idx < P5) {                       // hav_norm
            int i = idx - P4;
            int b = i / 28; int j = i - b*28;
            int k = 286 + j; if (k >= 307) k -= 7;
            v = val[b*28 + j] / g_Sfull[b*307 + k] / g_levels[b*TLEN + 299];
        }
        out[idx] = v;
    }
}

// ---------------- host launcher ----------------------------------------------
extern "C" void kernel_launch(void* const* d_in, const int* in_sizes, int n_in,
                              void* d_out, int out_size)
{
    const float* x      = (const float*)d_in[0];
    const float* val    = (const float*)d_in[1];
    const float* alpha  = (const float*)d_in[2];
    const float* gamma  = (const float*)d_in[3];
    const float* iseas  = (const float*)d_in[4];
    const float* cats   = (const float*)d_in[5];
    const float* myp    = (const float*)d_in[6];
    const float* Wih1   = (const float*)d_in[7];
    const float* Whh1   = (const float*)d_in[8];
    const float* b1     = (const float*)d_in[9];
    const float* Wih2   = (const float*)d_in[10];
    const float* Whh2   = (const float*)d_in[11];
    const float* b2     = (const float*)d_in[12];
    const float* Wih3   = (const float*)d_in[13];
    const float* Whh3   = (const float*)d_in[14];
    const float* b3     = (const float*)d_in[15];
    const float* Wih4   = (const float*)d_in[16];
    const float* Whh4   = (const float*)d_in[17];
    const float* b4     = (const float*)d_in[18];
    const float* lW     = (const float*)d_in[19];
    const float* lb     = (const float*)d_in[20];
    const float* sW     = (const float*)d_in[21];
    const float* sb     = (const float*)d_in[22];

    float *pWin, *pZ, *pHA, *pHB, *pRnn;
    cudaGetSymbolAddress((void**)&pWin, g_win);
    cudaGetSymbolAddress((void**)&pZ,   g_Z);
    cudaGetSymbolAddress((void**)&pHA,  g_hA);
    cudaGetSymbolAddress((void**)&pHB,  g_hB);
    cudaGetSymbolAddress((void**)&pRnn, g_rnn);

    // 1) exponential smoothing + seasonals
    es_kernel<<<1, 128>>>(x, alpha, gamma, iseas);

    // 2) normalized window inputs (batch collapsed to 10 distinct rows)
    build_win<<<(MROWS*FIN + 255)/256, 256>>>(x, cats, myp);

    dim3 gBig128(8, (MROWS + 127)/128);   // N=1024, K=256 GEMMs

    // ---- layer 1 (d=1): K=49 input GEMM, then 10 clusters x 1 chain ----
    sgemm_nt<0><<<dim3(16, (MROWS+63)/64), 256>>>(pWin, Wih1, b1, pZ, MROWS, 1024, FIN);
    lstm_chain<1,1><<<80, 256>>>(pZ, Whh1, pHA);

    // ---- layer 2 (d=2): 10 clusters x 2 phases -> hB (kept for residual) ----
    sgemm128<0><<<gBig128, 256>>>(pHA, Wih2, b2, pZ, MROWS, 1024, HN);
    lstm_chain<2,2><<<80, 256>>>(pZ, Whh2, pHB);

    // ---- layer 3 (d=2) ----
    sgemm128<0><<<gBig128, 256>>>(pHB, Wih3, b3, pZ, MROWS, 1024, HN);
    lstm_chain<2,2><<<80, 256>>>(pZ, Whh3, pHA);

    // ---- layer 4 (d=6): 15 clusters x 4 chains ----
    sgemm128<0><<<gBig128, 256>>>(pHA, Wih4, b4, pZ, MROWS, 1024, HN);
    lstm_chain<4,6><<<120, 256>>>(pZ, Whh4, pHA);

    // ---- residual: h2 = lstm4(...) + h1 ----
    add_residual<<<(MROWS*HN + 255)/256, 256>>>(pHA, pHB);

    // ---- linear + tanh, then score ----
    sgemm128<1><<<dim3(2, (MROWS+127)/128), 256>>>(pHA, lW, lb, pHB, MROWS, HN, HN);
    sgemm_nt<0><<<dim3(1, (MROWS+63)/64), 256>>>(pHB, sW, sb, pRnn, MROWS, OUTN, HN);

    // ---- assemble outputs ----
    outputs_kernel<<<1024, 256>>>(x, val, (float*)d_out, out_size);
}